// round 16
// baseline (speedup 1.0000x reference)
#include <cuda_runtime.h>
#include <cuda_fp16.h>
#include <math.h>
#include <stdint.h>

#define NN 100000
#define EE 1600000
#define FIN 64
#define EPSBN 1e-5f
#define NPAD 100096            // multiple of 128
#define NCTA (NPAD / 128)      // 782

// ---------------- scratch (device globals, no allocation) ----------------
__device__ int    g_off[NN + 1];
__device__ int    g_cur[NN];
__device__ int    g_srcs[EE];
__device__ float  g_sum[64];
__device__ float  g_ssq[64];
__device__ __align__(16) float g_scale[64];
__device__ __align__(16) float g_shift[64];
__device__ __half g_Wm2T[1024 * 1024];                 // 2 MB, [n][k], fp16
__device__ __half g_Wm1T[1024 * 32];                   // 64 KB, [n][k], fp16
__device__ __half g_WcT1[64 * 128];                    // [c][k] fp16, layer1
__device__ __half g_WcT2[32 * 128];                    // [c][k] fp16, layer2
__device__ uint32_t g_H1c[(size_t)NCTA * 16 * 4096];   // 205 MB: [cta][chunk][128][32w]

// ---------------- helpers ----------------
__device__ __forceinline__ void cp16(uint32_t dst, const void* src) {
    asm volatile("cp.async.cg.shared.global [%0], [%1], 16;" :: "r"(dst), "l"(src));
}
__device__ __forceinline__ void cp_commit() { asm volatile("cp.async.commit_group;" ::: "memory"); }
__device__ __forceinline__ void cp_wait0() { asm volatile("cp.async.wait_group 0;" ::: "memory"); }
__device__ __forceinline__ uint32_t smem_u32(const void* p) {
    uint32_t a;
    asm("{ .reg .u64 t; cvta.to.shared.u64 t, %1; cvt.u32.u64 %0, t; }" : "=r"(a) : "l"(p));
    return a;
}
__device__ __forceinline__ void mma16(float* c, const uint32_t* a, uint32_t b0, uint32_t b1) {
    asm volatile("mma.sync.aligned.m16n8k16.row.col.f32.f16.f16.f32 "
        "{%0,%1,%2,%3}, {%4,%5,%6,%7}, {%8,%9}, {%0,%1,%2,%3};"
        : "+f"(c[0]), "+f"(c[1]), "+f"(c[2]), "+f"(c[3])
        : "r"(a[0]), "r"(a[1]), "r"(a[2]), "r"(a[3]), "r"(b0), "r"(b1));
}
__device__ __forceinline__ void ldsm4(uint32_t* r, uint32_t addr) {
    asm volatile("ldmatrix.sync.aligned.m8n8.x4.shared.b16 {%0,%1,%2,%3}, [%4];"
        : "=r"(r[0]), "=r"(r[1]), "=r"(r[2]), "=r"(r[3]) : "r"(addr));
}

// ---------------- CSR build ----------------
__global__ void k0_zero() {
    int i = blockIdx.x * blockDim.x + threadIdx.x;
    int st = gridDim.x * blockDim.x;
    for (int j = i; j < NN; j += st) g_cur[j] = 0;
    if (i < 64) { g_sum[i] = 0.f; g_ssq[i] = 0.f; }
}
__global__ void khist(const int* __restrict__ ei, int E) {
    int i = blockIdx.x * blockDim.x + threadIdx.x;
    int st = gridDim.x * blockDim.x;
    for (int e = i; e < E; e += st) atomicAdd(&g_cur[ei[E + e]], 1);
}
__global__ void kscan(int E) {
    __shared__ int ssum[1024];
    int t = threadIdx.x;
    const int CH = (NN + 1023) / 1024;
    int beg = t * CH, end = min(beg + CH, NN);
    int s = 0;
    for (int j = beg; j < end; j++) s += g_cur[j];
    ssum[t] = s;
    __syncthreads();
    for (int d = 1; d < 1024; d <<= 1) {
        int v = (t >= d) ? ssum[t - d] : 0;
        __syncthreads();
        ssum[t] += v;
        __syncthreads();
    }
    int run = (t > 0) ? ssum[t - 1] : 0;
    for (int j = beg; j < end; j++) {
        int c = g_cur[j];
        g_off[j] = run;
        g_cur[j] = run;
        run += c;
    }
    if (t == 1023) g_off[NN] = E;
}
__global__ void kfill(const int* __restrict__ ei, int E) {
    int i = blockIdx.x * blockDim.x + threadIdx.x;
    int st = gridDim.x * blockDim.x;
    for (int e = i; e < E; e += st) {
        int pos = atomicAdd(&g_cur[ei[E + e]], 1);
        g_srcs[pos] = ei[e];
    }
}
__global__ void kzstats() {
    int i = threadIdx.x;
    if (i < 64) { g_sum[i] = 0.f; g_ssq[i] = 0.f; }
}

// ---------------- SAGE weight concat+transpose (fp16): dst[c][k] ----------
__global__ void ktransWc(const float* __restrict__ Wl, const float* __restrict__ Wr,
                         __half* __restrict__ dst, int FOUT) {
    int i = blockIdx.x * blockDim.x + threadIdx.x;
    if (i < FOUT * 128) {
        int c = i >> 7, k = i & 127;
        float v = (k < 64) ? Wl[k * FOUT + c] : Wr[(k - 64) * FOUT + c];
        dst[(size_t)c * 128 + k] = __float2half_rn(v);
    }
}

// ---------------- SAGE layer: tensor-core transform, fused CSR gather ------
// 128 nodes/CTA, 256 threads. sA [128][68w] fp16, sB [FOUT][68w] fp16.
#define SB_OFF 34816
template <int FOUT>
__global__ void __launch_bounds__(256)
klayer(const float* __restrict__ xin, const float* __restrict__ bl,
       const __half* __restrict__ WcatT,
       float* __restrict__ hout, int n_nodes) {
    extern __shared__ __align__(16) char dsm[];
    uint32_t sb = smem_u32(dsm);
    uint32_t* sAw = (uint32_t*)dsm;
    __shared__ float ssum[FOUT];
    __shared__ float sssq[FOUT];
    int tid = threadIdx.x;
    int lane = tid & 31, wid = tid >> 5;
    int nbase = blockIdx.x * 128;
    int r = tid >> 2;
    int q = tid & 3;
    if (tid < FOUT) { ssum[tid] = 0.f; sssq[tid] = 0.f; }

    // stage B = WcatT [FOUT][128 halves] into sB (stride 68 words)
    for (int i = tid; i < FOUT * 16; i += 256) {
        int row = i >> 4, seg = i & 15;
        cp16(sb + SB_OFF + row * 272 + seg * 16, WcatT + (size_t)row * 128 + seg * 8);
    }
    cp_commit();

    // gather + fp16 staging into sA (2 nodes/thread; 16 ch/thread per node)
#pragma unroll
    for (int pp = 0; pp < 2; pp++) {
        int rr = r + pp * 64;
        int n = nbase + rr;
        bool ok = n < n_nodes;
        float4 v0, v1, v2, v3;
        {
            const float4* xr = (const float4*)(xin + (size_t)(ok ? n : 0) * 64 + q * 16);
            v0 = ok ? xr[0] : make_float4(0, 0, 0, 0);
            v1 = ok ? xr[1] : make_float4(0, 0, 0, 0);
            v2 = ok ? xr[2] : make_float4(0, 0, 0, 0);
            v3 = ok ? xr[3] : make_float4(0, 0, 0, 0);
        }
        float a0[4] = {0, 0, 0, 0}, a1[4] = {0, 0, 0, 0};
        float a2[4] = {0, 0, 0, 0}, a3[4] = {0, 0, 0, 0};
        int beg = 0, end = 0;
        if (ok) { beg = g_off[n]; end = g_off[n + 1]; }
        int e = beg;
        for (; e + 2 <= end; e += 2) {
            const float4* p0 = (const float4*)(xin + (size_t)g_srcs[e] * 64 + q * 16);
            const float4* p1 = (const float4*)(xin + (size_t)g_srcs[e + 1] * 64 + q * 16);
            float4 u0 = p0[0], u1 = p0[1], u2 = p0[2], u3 = p0[3];
            float4 w0 = p1[0], w1 = p1[1], w2 = p1[2], w3 = p1[3];
            a0[0] += u0.x + w0.x; a0[1] += u0.y + w0.y; a0[2] += u0.z + w0.z; a0[3] += u0.w + w0.w;
            a1[0] += u1.x + w1.x; a1[1] += u1.y + w1.y; a1[2] += u1.z + w1.z; a1[3] += u1.w + w1.w;
            a2[0] += u2.x + w2.x; a2[1] += u2.y + w2.y; a2[2] += u2.z + w2.z; a2[3] += u2.w + w2.w;
            a3[0] += u3.x + w3.x; a3[1] += u3.y + w3.y; a3[2] += u3.z + w3.z; a3[3] += u3.w + w3.w;
        }
        if (e < end) {
            const float4* p0 = (const float4*)(xin + (size_t)g_srcs[e] * 64 + q * 16);
            float4 u0 = p0[0], u1 = p0[1], u2 = p0[2], u3 = p0[3];
            a0[0] += u0.x; a0[1] += u0.y; a0[2] += u0.z; a0[3] += u0.w;
            a1[0] += u1.x; a1[1] += u1.y; a1[2] += u1.z; a1[3] += u1.w;
            a2[0] += u2.x; a2[1] += u2.y; a2[2] += u2.z; a2[3] += u2.w;
            a3[0] += u3.x; a3[1] += u3.y; a3[2] += u3.z; a3[3] += u3.w;
        }
        float inv = 1.f / fmaxf((float)(end - beg), 1.f);
        uint32_t base = rr * 68;
        __half2 h;
        // mean -> k cols 0..63 (words 0..31)
        h = __floats2half2_rn(a0[0] * inv, a0[1] * inv); sAw[base + q * 8 + 0] = *(uint32_t*)&h;
        h = __floats2half2_rn(a0[2] * inv, a0[3] * inv); sAw[base + q * 8 + 1] = *(uint32_t*)&h;
        h = __floats2half2_rn(a1[0] * inv, a1[1] * inv); sAw[base + q * 8 + 2] = *(uint32_t*)&h;
        h = __floats2half2_rn(a1[2] * inv, a1[3] * inv); sAw[base + q * 8 + 3] = *(uint32_t*)&h;
        h = __floats2half2_rn(a2[0] * inv, a2[1] * inv); sAw[base + q * 8 + 4] = *(uint32_t*)&h;
        h = __floats2half2_rn(a2[2] * inv, a2[3] * inv); sAw[base + q * 8 + 5] = *(uint32_t*)&h;
        h = __floats2half2_rn(a3[0] * inv, a3[1] * inv); sAw[base + q * 8 + 6] = *(uint32_t*)&h;
        h = __floats2half2_rn(a3[2] * inv, a3[3] * inv); sAw[base + q * 8 + 7] = *(uint32_t*)&h;
        // x -> k cols 64..127 (words 32..63)
        h = __floats2half2_rn(v0.x, v0.y); sAw[base + 32 + q * 8 + 0] = *(uint32_t*)&h;
        h = __floats2half2_rn(v0.z, v0.w); sAw[base + 32 + q * 8 + 1] = *(uint32_t*)&h;
        h = __floats2half2_rn(v1.x, v1.y); sAw[base + 32 + q * 8 + 2] = *(uint32_t*)&h;
        h = __floats2half2_rn(v1.z, v1.w); sAw[base + 32 + q * 8 + 3] = *(uint32_t*)&h;
        h = __floats2half2_rn(v2.x, v2.y); sAw[base + 32 + q * 8 + 4] = *(uint32_t*)&h;
        h = __floats2half2_rn(v2.z, v2.w); sAw[base + 32 + q * 8 + 5] = *(uint32_t*)&h;
        h = __floats2half2_rn(v3.x, v3.y); sAw[base + 32 + q * 8 + 6] = *(uint32_t*)&h;
        h = __floats2half2_rn(v3.z, v3.w); sAw[base + 32 + q * 8 + 7] = *(uint32_t*)&h;
    }
    cp_wait0();
    __syncthreads();

    // ---- mma: h[128][FOUT] = A[128][128] @ B^T, 16 rows/warp ----
    float acc[FOUT / 8][4];
#pragma unroll
    for (int nf = 0; nf < FOUT / 8; nf++)
#pragma unroll
        for (int e2 = 0; e2 < 4; e2++) acc[nf][e2] = 0.f;

    uint32_t aB = sb + ((uint32_t)(wid * 16 + (lane & 7) + ((lane >> 3) & 1) * 8) * 68
                        + ((lane >> 4) & 1) * 4) * 4;
    uint32_t bB = sb + SB_OFF + ((uint32_t)((lane & 7) + ((lane >> 4) & 1) * 8) * 68
                        + ((lane >> 3) & 1) * 4) * 4;
#pragma unroll
    for (int ks = 0; ks < 8; ks++) {
        uint32_t a[4];
        ldsm4(a, aB + ks * 32);
#pragma unroll
        for (int nfp = 0; nfp < FOUT / 16; nfp++) {
            uint32_t bf[4];
            ldsm4(bf, bB + (nfp * 16 * 68 + ks * 8) * 4);
            mma16(acc[2 * nfp],     a, bf[0], bf[1]);
            mma16(acc[2 * nfp + 1], a, bf[2], bf[3]);
        }
    }

    // ---- epilogue: bias, store h, BN stats ----
    int g_ = lane >> 2, c4 = lane & 3;
    int r0 = wid * 16 + g_;
    int n0 = nbase + r0, n1 = n0 + 8;
#pragma unroll
    for (int nf = 0; nf < FOUT / 8; nf++) {
        int col = nf * 8 + c4 * 2;
        float2 bv = *(const float2*)&bl[col];
        float h0 = acc[nf][0] + bv.x, h1 = acc[nf][1] + bv.y;
        float h2 = acc[nf][2] + bv.x, h3 = acc[nf][3] + bv.y;
        if (n0 < n_nodes) {
            *(float2*)&hout[(size_t)n0 * FOUT + col] = make_float2(h0, h1);
            atomicAdd(&ssum[col], h0);     atomicAdd(&ssum[col + 1], h1);
            atomicAdd(&sssq[col], h0 * h0); atomicAdd(&sssq[col + 1], h1 * h1);
        }
        if (n1 < n_nodes) {
            *(float2*)&hout[(size_t)n1 * FOUT + col] = make_float2(h2, h3);
            atomicAdd(&ssum[col], h2);     atomicAdd(&ssum[col + 1], h3);
            atomicAdd(&sssq[col], h2 * h2); atomicAdd(&sssq[col + 1], h3 * h3);
        }
    }
    __syncthreads();
    if (tid < FOUT) {
        atomicAdd(&g_sum[tid], ssum[tid]);
        atomicAdd(&g_ssq[tid], sssq[tid]);
    }
}

// ---------------- BN finalize + apply (float4) ----------------
__global__ void kfinal(const float* __restrict__ g, const float* __restrict__ be,
                       int F, float invN) {
    int t = threadIdx.x;
    if (t >= F) return;
    float mu = g_sum[t] * invN;
    float var = fmaxf(g_ssq[t] * invN - mu * mu, 0.f);
    float sc = g[t] * rsqrtf(var + EPSBN);
    g_scale[t] = sc;
    g_shift[t] = be[t] - mu * sc;
}

__global__ void kbn(float* __restrict__ h, long long total4, int Fmask) {
    long long i = (long long)blockIdx.x * blockDim.x + threadIdx.x;
    if (i < total4) {
        long long i4 = i * 4;
        int c = (int)(i4 & Fmask);
        float4 v = *(float4*)&h[i4];
        float4 sc = *(float4*)&g_scale[c];
        float4 sh = *(float4*)&g_shift[c];
        v.x = fmaxf(v.x * sc.x + sh.x, 0.f);
        v.y = fmaxf(v.y * sc.y + sh.y, 0.f);
        v.z = fmaxf(v.z * sc.z + sh.z, 0.f);
        v.w = fmaxf(v.w * sc.w + sh.w, 0.f);
        *(float4*)&h[i4] = v;
    }
}

// ---------------- weight transposes (fp16) ----------------
__global__ void ktrans(const float* __restrict__ Wm2) {
    __shared__ float tile[32][33];
    int tx = threadIdx.x, ty = threadIdx.y;
    int bx = blockIdx.x, by = blockIdx.y;
#pragma unroll
    for (int i = 0; i < 4; i++)
        tile[ty + i * 8][tx] = Wm2[(by * 32 + ty + i * 8) * 1024 + bx * 32 + tx];
    __syncthreads();
#pragma unroll
    for (int i = 0; i < 4; i++)
        g_Wm2T[(size_t)(bx * 32 + ty + i * 8) * 1024 + by * 32 + tx] =
            __float2half_rn(tile[tx][ty + i * 8]);
}
__global__ void ktransW1(const float* __restrict__ Wm1) {
    int i = blockIdx.x * blockDim.x + threadIdx.x;
    if (i < 1024 * 32) {
        int n = i >> 5, k = i & 31;
        g_Wm1T[n * 32 + k] = __float2half_rn(Wm1[k * 1024 + n]);
    }
}

// ---------------- fused MLP: GEMM1 cached after nt=0, ldmatrix, 1-sync loop --
#define OFF_A    0                       // [128][36w] x2         36864
#define OFF_B20  36864                   // [256][36w] x2         73728
#define OFF_XH   110592                  // [128][20w]            10240
#define OFF_B10  120832                  // [64][20w] x2          10240
#define OFF_BM1  131072                  // 1024 f32               4096
#define OFF_W3H  135168                  // [16][132w] fp16x2      8448
#define OFF_BM2  143616                  // 256 f32                1024
#define MLP3_SMEM 144640

__global__ void __launch_bounds__(256, 1)
kmlp3(const float* __restrict__ xt2, const float* __restrict__ bm1,
      const float* __restrict__ bm2,
      const float* __restrict__ Wm3, const float* __restrict__ bm3,
      float* __restrict__ out_sm, float* __restrict__ out_lg, int n_nodes) {
    extern __shared__ __align__(16) char smem[];
    uint32_t sb = smem_u32(smem);
    float* sBm2 = (float*)(smem + OFF_BM2);
    float* sBm1 = (float*)(smem + OFF_BM1);
    uint32_t* sXw  = (uint32_t*)(smem + OFF_XH);
    uint32_t* sW3w = (uint32_t*)(smem + OFF_W3H);

    int t = threadIdx.x;
    int lane = t & 31;
    int wid = t >> 5;
    int wm = wid >> 2;
    int wn = wid & 3;
    int g = lane >> 2;
    int c4 = lane & 3;
    int base_m = blockIdx.x * 128;
    uint32_t* h1c = g_H1c + (size_t)blockIdx.x * 16 * 4096;

    uint32_t aBase = ((uint32_t)(wm * 64 + (lane & 7) + ((lane >> 3) & 1) * 8) * 36
                      + ((lane >> 4) & 1) * 4) * 4;
    uint32_t bBase = ((uint32_t)(wn * 64 + (lane & 7) + ((lane >> 4) & 1) * 8) * 36
                      + ((lane >> 3) & 1) * 4) * 4;

    // ---- stage X tile + bm1 ----
    for (int i = t; i < 128 * 16; i += 256) {
        int row = i >> 4, w = i & 15;
        int m = base_m + row;
        float f0 = 0.f, f1 = 0.f;
        if (m < n_nodes) {
            const float2 v = *(const float2*)(xt2 + (size_t)m * 32 + w * 2);
            f0 = v.x; f1 = v.y;
        }
        __half2 h = __floats2half2_rn(f0, f1);
        sXw[row * 20 + w] = *(uint32_t*)&h;
    }
    for (int i = t; i < 1024; i += 256) sBm1[i] = bm1[i];

    float L[4][2][4];
#pragma unroll
    for (int mf = 0; mf < 4; mf++)
#pragma unroll
        for (int h = 0; h < 2; h++)
#pragma unroll
            for (int e = 0; e < 4; e++) L[mf][h][e] = 0.f;

    for (int nt = 0; nt < 4; nt++) {
        if (t < 256) sBm2[t] = bm2[nt * 256 + t];
        for (int i = t; i < 2048; i += 256) {
            int o = i >> 7, kw = i & 127;
            int kg = nt * 256 + kw * 2;
            __half2 h = __floats2half2_rn(Wm3[(size_t)kg * 16 + o],
                                          Wm3[(size_t)(kg + 1) * 16 + o]);
            sW3w[o * 132 + kw] = *(uint32_t*)&h;
        }

        float acc[4][8][4];
#pragma unroll
        for (int mf = 0; mf < 4; mf++)
#pragma unroll
            for (int nf = 0; nf < 8; nf++)
#pragma unroll
                for (int e = 0; e < 4; e++) acc[mf][nf][e] = 0.f;

        if (nt == 0) {
            // ====== nt=0: compute GEMM1, cache H1 chunks ======
            {
                uint32_t b1off = sb + OFF_B10;
                if (t < 256) {
                    int row = t >> 2, c = t & 3;
                    cp16(b1off + row * 80 + c * 16, g_Wm1T + (size_t)row * 32 + c * 8);
                }
                cp_commit();
                uint32_t boff = sb + OFF_B20;
                for (int i = t; i < 2048; i += 256) {
                    int row = i >> 3, c = i & 7;
                    cp16(boff + row * 144 + c * 16,
                         g_Wm2T + (size_t)row * 1024 + c * 8);
                }
                uint32_t b1off1 = sb + OFF_B10 + 5120;
                if (t < 256) {
                    int row = t >> 2, c = t & 3;
                    cp16(b1off1 + row * 80 + c * 16,
                         g_Wm1T + (size_t)(64 + row) * 32 + c * 8);
                }
                cp_commit();
            }
            cp_wait0();
            __syncthreads();

            // GEMM1(0) -> sA[0] + g_H1c[0]
            {
                const uint32_t* B1 = (const uint32_t*)(smem + OFF_B10);
                uint32_t* sAw = (uint32_t*)(smem + OFF_A);
                float cc[8][4];
#pragma unroll
                for (int nf = 0; nf < 8; nf++)
#pragma unroll
                    for (int e = 0; e < 4; e++) cc[nf][e] = 0.f;
#pragma unroll
                for (int ks = 0; ks < 2; ks++) {
                    uint32_t a[4];
                    int r0 = wid * 16 + g;
                    a[0] = sXw[r0 * 20 + ks * 8 + c4];
                    a[1] = sXw[(r0 + 8) * 20 + ks * 8 + c4];
                    a[2] = sXw[r0 * 20 + ks * 8 + c4 + 4];
                    a[3] = sXw[(r0 + 8) * 20 + ks * 8 + c4 + 4];
#pragma unroll
                    for (int nf = 0; nf < 8; nf++) {
                        int nr = nf * 8 + g;
                        mma16(cc[nf], a, B1[nr * 20 + ks * 8 + c4], B1[nr * 20 + ks * 8 + c4 + 4]);
                    }
                }
                int r0 = wid * 16 + g;
#pragma unroll
                for (int nf = 0; nf < 8; nf++) {
                    int col = nf * 8 + c4 * 2;
                    float2 bv = *(const float2*)&sBm1[col];
                    __half2 p0 = __floats2half2_rn(fmaxf(cc[nf][0] + bv.x, 0.f),
                                                   fmaxf(cc[nf][1] + bv.y, 0.f));
                    __half2 p1 = __floats2half2_rn(fmaxf(cc[nf][2] + bv.x, 0.f),
                                                   fmaxf(cc[nf][3] + bv.y, 0.f));
                    sAw[r0 * 36 + nf * 4 + c4] = *(uint32_t*)&p0;
                    sAw[(r0 + 8) * 36 + nf * 4 + c4] = *(uint32_t*)&p1;
                    h1c[r0 * 32 + nf * 4 + c4] = *(uint32_t*)&p0;
                    h1c[(r0 + 8) * 32 + nf * 4 + c4] = *(uint32_t*)&p1;
                }
            }

            for (int kc = 0; kc < 16; kc++) {
                __syncthreads();
                if (kc < 15) {
                    uint32_t boff = sb + OFF_B20 + ((kc + 1) & 1) * 36864;
                    int kbase = (kc + 1) * 64;
                    for (int i = t; i < 2048; i += 256) {
                        int row = i >> 3, c = i & 7;
                        cp16(boff + row * 144 + c * 16,
                             g_Wm2T + (size_t)row * 1024 + kbase + c * 8);
                    }
                    if (kc + 2 <= 15) {
                        uint32_t b1off = sb + OFF_B10 + (kc & 1) * 5120;
                        if (t < 256) {
                            int row = t >> 2, c = t & 3;
                            cp16(b1off + row * 80 + c * 16,
                                 g_Wm1T + (size_t)((kc + 2) * 64 + row) * 32 + c * 8);
                        }
                    }
                    cp_commit();
                }
                // GEMM2(kc) via ldmatrix
                {
                    uint32_t Ab = sb + OFF_A + (kc & 1) * 18432u;
                    uint32_t Bb = sb + OFF_B20 + (kc & 1) * 36864u;
#pragma unroll
                    for (int ks = 0; ks < 4; ks++) {
                        uint32_t a[4][4];
#pragma unroll
                        for (int mf = 0; mf < 4; mf++)
                            ldsm4(a[mf], Ab + aBase + (mf * 576 + ks * 8) * 4);
#pragma unroll
                        for (int nfp = 0; nfp < 4; nfp++) {
                            uint32_t bf[4];
                            ldsm4(bf, Bb + bBase + (nfp * 576 + ks * 8) * 4);
#pragma unroll
                            for (int mf = 0; mf < 4; mf++) {
                                mma16(acc[mf][2 * nfp],     a[mf], bf[0], bf[1]);
                                mma16(acc[mf][2 * nfp + 1], a[mf], bf[2], bf[3]);
                            }
                        }
                    }
                }
                // GEMM1(kc+1)
                if (kc < 15) {
                    const uint32_t* B1 = (const uint32_t*)(smem + OFF_B10 + ((kc + 1) & 1) * 5120);
                    uint32_t* sAw = (uint32_t*)(smem + OFF_A + ((kc + 1) & 1) * 18432);
                    uint32_t* hc = h1c + (size_t)(kc + 1) * 4096;
                    float cc[8][4];
#pragma unroll
                    for (int nf = 0; nf < 8; nf++)
#pragma unroll
                        for (int e = 0; e < 4; e++) cc[nf][e] = 0.f;
#pragma unroll
                    for (int ks = 0; ks < 2; ks++) {
                        uint32_t a[4];
                        int r0 = wid * 16 + g;
                        a[0] = sXw[r0 * 20 + ks * 8 + c4];
                        a[1] = sXw[(r0 + 8) * 20 + ks * 8 + c4];
                        a[2] = sXw[r0 * 20 + ks * 8 + c4 + 4];
                        a[3] = sXw[(r0 + 8) * 20 + ks * 8 + c4 + 4];
#pragma unroll
                        for (int nf = 0; nf < 8; nf++) {
                            int nr = nf * 8 + g;
                            mma16(cc[nf], a, B1[nr * 20 + ks * 8 + c4], B1[nr * 20 + ks * 8 + c4 + 4]);
                        }
                    }
                    int r0 = wid * 16 + g;
#pragma unroll
                    for (int nf = 0; nf < 8; nf++) {
                        int col = (kc + 1) * 64 + nf * 8 + c4 * 2;
                        float2 bv = *(const float2*)&sBm1[col];
                        __half2 p0 = __floats2half2_rn(fmaxf(cc[nf][0] + bv.x, 0.f),
                                                       fmaxf(cc[nf][1] + bv.y, 0.f));
                        __half2 p1 = __floats2half2_rn(fmaxf(cc[nf][2] + bv.x, 0.f),
                                                       fmaxf(cc[nf][3] + bv.y, 0.f));
                        sAw[r0 * 36 + nf * 4 + c4] = *(uint32_t*)&p0;
                        sAw[(r0 + 8) * 36 + nf * 4 + c4] = *(uint32_t*)&p1;
                        hc[r0 * 32 + nf * 4 + c4] = *(uint32_t*)&p0;
                        hc[(r0 + 8) * 32 + nf * 4 + c4] = *(uint32_t*)&p1;
                    }
                }
                cp_wait0();
            }
        } else {
            // ====== nt>=1: cached H1, single-sync pipelined loop ======
            {
                uint32_t aoff = sb + OFF_A;
                const uint32_t* src = h1c;
                for (int i = t; i < 1024; i += 256) {
                    int row = i >> 3, c = i & 7;
                    cp16(aoff + row * 144 + c * 16, src + row * 32 + c * 4);
                }
                uint32_t boff = sb + OFF_B20;
                for (int i = t; i < 2048; i += 256) {
                    int row = i >> 3, c = i & 7;
                    cp16(boff + row * 144 + c * 16,
                         g_Wm2T + (size_t)(nt * 256 + row) * 1024 + c * 8);
                }
                cp_commit();
            }
            cp_wait0();
            for (int kc = 0; kc < 16; kc++) {
                __syncthreads();
                if (kc < 15) {
                    int k2 = kc + 1;
                    uint32_t aoff = sb + OFF_A + (k2 & 1) * 18432;
                    const uint32_t* src = h1c + (size_t)k2 * 4096;
                    for (int i = t; i < 1024; i += 256) {
                        int row = i >> 3, c = i & 7;
                        cp16(aoff + row * 144 + c * 16, src + row * 32 + c * 4);
                    }
                    uint32_t boff = sb + OFF_B20 + (k2 & 1) * 36864;
                    for (int i = t; i < 2048; i += 256) {
                        int row = i >> 3, c = i & 7;
                        cp16(boff + row * 144 + c * 16,
                             g_Wm2T + (size_t)(nt * 256 + row) * 1024 + k2 * 64 + c * 8);
                    }
                    cp_commit();
                }
                {
                    uint32_t Ab = sb + OFF_A + (kc & 1) * 18432u;
                    uint32_t Bb = sb + OFF_B20 + (kc & 1) * 36864u;
#pragma unroll
                    for (int ks = 0; ks < 4; ks++) {
                        uint32_t a[4][4];
#pragma unroll
                        for (int mf = 0; mf < 4; mf++)
                            ldsm4(a[mf], Ab + aBase + (mf * 576 + ks * 8) * 4);
#pragma unroll
                        for (int nfp = 0; nfp < 4; nfp++) {
                            uint32_t bf[4];
                            ldsm4(bf, Bb + bBase + (nfp * 576 + ks * 8) * 4);
#pragma unroll
                            for (int mf = 0; mf < 4; mf++) {
                                mma16(acc[mf][2 * nfp],     a[mf], bf[0], bf[1]);
                                mma16(acc[mf][2 * nfp + 1], a[mf], bf[2], bf[3]);
                            }
                        }
                    }
                }
                cp_wait0();
            }
        }

        // ---- GEMM3: logits += relu(acc + bm2) @ Wm3 ----
        {
            uint32_t b0f[4][2], b1f[4][2];
#pragma unroll
            for (int j = 0; j < 4; j++) {
                int kq = wn * 32 + 8 * j + c4;
#pragma unroll
                for (int h = 0; h < 2; h++) {
                    b0f[j][h] = sW3w[(h * 8 + g) * 132 + kq];
                    b1f[j][h] = sW3w[(h * 8 + g) * 132 + kq + 4];
                }
            }
#pragma unroll
            for (int j = 0; j < 4; j++) {
                int cA = wn * 64 + 16 * j + 2 * c4;
                float2 bva = *(const float2*)&sBm2[cA];
                float2 bvb = *(const float2*)&sBm2[cA + 8];
#pragma unroll
                for (int mf = 0; mf < 4; mf++) {
                    __half2 ha0 = __floats2half2_rn(fmaxf(acc[mf][2 * j][0] + bva.x, 0.f),
                                                    fmaxf(acc[mf][2 * j][1] + bva.y, 0.f));
                    __half2 ha1 = __floats2half2_rn(fmaxf(acc[mf][2 * j][2] + bva.x, 0.f),
                                                    fmaxf(acc[mf][2 * j][3] + bva.y, 0.f));
                    __half2 ha2 = __floats2half2_rn(fmaxf(acc[mf][2 * j + 1][0] + bvb.x, 0.f),
                                                    fmaxf(acc[mf][2 * j + 1][1] + bvb.y, 0.f));
                    __half2 ha3 = __floats2half2_rn(fmaxf(acc[mf][2 * j + 1][2] + bvb.x, 0.f),
                                                    fmaxf(acc[mf][2 * j + 1][3] + bvb.y, 0.f));
                    uint32_t a[4] = {*(uint32_t*)&ha0, *(uint32_t*)&ha1,
                                     *(uint32_t*)&ha2, *(uint32_t*)&ha3};
#pragma unroll
                    for (int h = 0; h < 2; h++)
                        mma16(L[mf][h], a, b0f[j][h], b1f[j][h]);
                }
            }
        }
        __syncthreads();
    }

    // ---- cross-warp logits reduce ----
    float* sLg = (float*)smem;
    for (int i = t; i < 2048; i += 256) sLg[i] = 0.f;
    __syncthreads();
#pragma unroll
    for (int mf = 0; mf < 4; mf++) {
        int R = wm * 64 + mf * 16 + g;
#pragma unroll
        for (int h = 0; h < 2; h++) {
            int col = h * 8 + 2 * c4;
            atomicAdd(&sLg[R * 16 + col],           L[mf][h][0]);
            atomicAdd(&sLg[R * 16 + col + 1],       L[mf][h][1]);
            atomicAdd(&sLg[(R + 8) * 16 + col],     L[mf][h][2]);
            atomicAdd(&sLg[(R + 8) * 16 + col + 1], L[mf][h][3]);
        }
    }
    __syncthreads();

    // ---- bias + softmax + store ----
    {
        int row = t >> 1, oh = t & 1;
        long long m = base_m + row;
        float lg8[8];
#pragma unroll
        for (int j = 0; j < 8; j++) lg8[j] = sLg[row * 16 + oh * 8 + j] + bm3[oh * 8 + j];
        float mx = lg8[0];
#pragma unroll
        for (int j = 1; j < 8; j++) mx = fmaxf(mx, lg8[j]);
        mx = fmaxf(mx, __shfl_xor_sync(0xffffffffu, mx, 1));
        float e[8];
        float s = 0.f;
#pragma unroll
        for (int j = 0; j < 8; j++) { e[j] = expf(lg8[j] - mx); s += e[j]; }
        s += __shfl_xor_sync(0xffffffffu, s, 1);
        float inv = 1.f / s;
        if (m < n_nodes) {
            float4* po = (float4*)&out_lg[m * 16 + oh * 8];
            float4* ps = (float4*)&out_sm[m * 16 + oh * 8];
            po[0] = make_float4(lg8[0], lg8[1], lg8[2], lg8[3]);
            po[1] = make_float4(lg8[4], lg8[5], lg8[6], lg8[7]);
            ps[0] = make_float4(e[0] * inv, e[1] * inv, e[2] * inv, e[3] * inv);
            ps[1] = make_float4(e[4] * inv, e[5] * inv, e[6] * inv, e[7] * inv);
        }
    }
}

// ---------------- launch ----------------
extern "C" void kernel_launch(void* const* d_in, const int* in_sizes, int n_in,
                              void* d_out, int out_size) {
    const float* x   = (const float*)d_in[0];
    const int*   ei  = (const int*)d_in[1];
    const float* W1l = (const float*)d_in[2];
    const float* b1l = (const float*)d_in[3];
    const float* W1r = (const float*)d_in[4];
    const float* g1  = (const float*)d_in[5];
    const float* be1 = (const float*)d_in[6];
    const float* W2l = (const float*)d_in[7];
    const float* b2l = (const float*)d_in[8];
    const float* W2r = (const float*)d_in[9];
    const float* g2  = (const float*)d_in[10];
    const float* be2 = (const float*)d_in[11];
    const float* Wm1 = (const float*)d_in[12];
    const float* bm1 = (const float*)d_in[13];
    const float* Wm2 = (const float*)d_in[14];
    const float* bm2 = (const float*)d_in[15];
    const float* Wm3 = (const float*)d_in[16];
    const float* bm3 = (const float*)d_in[17];

    const int n = in_sizes[0] / FIN;             // 100000
    const int E = in_sizes[1] / 2;               // 1600000

    float* out = (float*)d_out;
    float* out_sm = out;
    float* out_lg = out + (long long)n * 16;
    float* xt1    = out + (long long)n * 32;
    float* xt2    = out + (long long)n * 96;

    const float invN = 1.f / (float)n;
    const int layer_grid = (n + 127) / 128;
    const int LAY1_SMEM = 34816 + 64 * 272;      // 52224
    const int LAY2_SMEM = 34816 + 32 * 272;      // 43520

    cudaFuncSetAttribute(kmlp3, cudaFuncAttributeMaxDynamicSharedMemorySize, MLP3_SMEM);
    cudaFuncSetAttribute(klayer<64>, cudaFuncAttributeMaxDynamicSharedMemorySize, LAY1_SMEM);
    cudaFuncSetAttribute(klayer<32>, cudaFuncAttributeMaxDynamicSharedMemorySize, LAY2_SMEM);

    __half* wct1; cudaGetSymbolAddress((void**)&wct1, g_WcT1);
    __half* wct2; cudaGetSymbolAddress((void**)&wct2, g_WcT2);

    // ----- CSR build + weight prep -----
    k0_zero<<<512, 256>>>();
    khist<<<1024, 256>>>(ei, E);
    ktransWc<<<32, 256>>>(W1l, W1r, wct1, 64);
    ktransWc<<<16, 256>>>(W2l, W2r, wct2, 32);
    kscan<<<1, 1024>>>(E);
    kfill<<<1024, 256>>>(ei, E);

    // ----- layer 1 -----
    kzstats<<<1, 64>>>();
    klayer<64><<<layer_grid, 256, LAY1_SMEM>>>(x, b1l, wct1, xt1, n);
    kfinal<<<1, 64>>>(g1, be1, 64, invN);
    kbn<<<(int)(((long long)n * 16 + 255) / 256), 256>>>(xt1, (long long)n * 16, 63);

    // ----- layer 2 -----
    kzstats<<<1, 64>>>();
    klayer<32><<<layer_grid, 256, LAY2_SMEM>>>(xt1, b2l, wct2, xt2, n);
    kfinal<<<1, 32>>>(g2, be2, 32, invN);
    kbn<<<(int)(((long long)n * 8 + 255) / 256), 256>>>(xt2, (long long)n * 8, 31);

    // ----- fused MLP -----
    dim3 tb(32, 8);
    dim3 tg(32, 32);
    ktrans<<<tg, tb>>>(Wm2);
    ktransW1<<<128, 256>>>(Wm1);
    kmlp3<<<NPAD / 128, 256, MLP3_SMEM>>>(xt2, bm1, bm2, Wm3, bm3, out_sm, out_lg, n);
}

// round 17
// speedup vs baseline: 1.4351x; 1.4351x over previous
#include <cuda_runtime.h>
#include <cuda_fp16.h>
#include <math.h>
#include <stdint.h>

#define NN 100000
#define EE 1600000
#define FIN 64
#define EPSBN 1e-5f
#define NPAD 100096            // multiple of 128
#define NCTA (NPAD / 128)      // 782

// ---------------- scratch (device globals, no allocation) ----------------
__device__ int    g_off[NN + 1];
__device__ int    g_cur[NN];
__device__ int    g_srcs[EE];
__device__ float  g_sum[64];
__device__ float  g_ssq[64];
__device__ __align__(16) float g_scale[64];
__device__ __align__(16) float g_shift[64];
__device__ __half g_Wm2T[1024 * 1024];                 // 2 MB, [n][k], fp16
__device__ __half g_Wm1T[1024 * 32];                   // 64 KB, [n][k], fp16
__device__ uint32_t g_H1c[(size_t)NCTA * 16 * 4096];   // 205 MB: [cta][chunk][128][32w]

// ---------------- helpers ----------------
__device__ __forceinline__ void cp16(uint32_t dst, const void* src) {
    asm volatile("cp.async.cg.shared.global [%0], [%1], 16;" :: "r"(dst), "l"(src));
}
__device__ __forceinline__ void cp_commit() { asm volatile("cp.async.commit_group;" ::: "memory"); }
__device__ __forceinline__ void cp_wait0() { asm volatile("cp.async.wait_group 0;" ::: "memory"); }
__device__ __forceinline__ uint32_t smem_u32(const void* p) {
    uint32_t a;
    asm("{ .reg .u64 t; cvta.to.shared.u64 t, %1; cvt.u32.u64 %0, t; }" : "=r"(a) : "l"(p));
    return a;
}
__device__ __forceinline__ void mma16(float* c, const uint32_t* a, uint32_t b0, uint32_t b1) {
    asm volatile("mma.sync.aligned.m16n8k16.row.col.f32.f16.f16.f32 "
        "{%0,%1,%2,%3}, {%4,%5,%6,%7}, {%8,%9}, {%0,%1,%2,%3};"
        : "+f"(c[0]), "+f"(c[1]), "+f"(c[2]), "+f"(c[3])
        : "r"(a[0]), "r"(a[1]), "r"(a[2]), "r"(a[3]), "r"(b0), "r"(b1));
}
__device__ __forceinline__ void ldsm4(uint32_t* r, uint32_t addr) {
    asm volatile("ldmatrix.sync.aligned.m8n8.x4.shared.b16 {%0,%1,%2,%3}, [%4];"
        : "=r"(r[0]), "=r"(r[1]), "=r"(r[2]), "=r"(r[3]) : "r"(addr));
}

// ---------------- CSR build ----------------
__global__ void k0_zero() {
    int i = blockIdx.x * blockDim.x + threadIdx.x;
    int st = gridDim.x * blockDim.x;
    for (int j = i; j < NN; j += st) g_cur[j] = 0;
    if (i < 64) { g_sum[i] = 0.f; g_ssq[i] = 0.f; }
}
__global__ void khist(const int* __restrict__ ei, int E) {
    int i = blockIdx.x * blockDim.x + threadIdx.x;
    int st = gridDim.x * blockDim.x;
    for (int e = i; e < E; e += st) atomicAdd(&g_cur[ei[E + e]], 1);
}
__global__ void kscan(int E) {
    __shared__ int ssum[1024];
    int t = threadIdx.x;
    const int CH = (NN + 1023) / 1024;
    int beg = t * CH, end = min(beg + CH, NN);
    int s = 0;
    for (int j = beg; j < end; j++) s += g_cur[j];
    ssum[t] = s;
    __syncthreads();
    for (int d = 1; d < 1024; d <<= 1) {
        int v = (t >= d) ? ssum[t - d] : 0;
        __syncthreads();
        ssum[t] += v;
        __syncthreads();
    }
    int run = (t > 0) ? ssum[t - 1] : 0;
    for (int j = beg; j < end; j++) {
        int c = g_cur[j];
        g_off[j] = run;
        g_cur[j] = run;
        run += c;
    }
    if (t == 1023) g_off[NN] = E;
}
__global__ void kfill(const int* __restrict__ ei, int E) {
    int i = blockIdx.x * blockDim.x + threadIdx.x;
    int st = gridDim.x * blockDim.x;
    for (int e = i; e < E; e += st) {
        int pos = atomicAdd(&g_cur[ei[E + e]], 1);
        g_srcs[pos] = ei[e];
    }
}
__global__ void kzstats() {
    int i = threadIdx.x;
    if (i < 64) { g_sum[i] = 0.f; g_ssq[i] = 0.f; }
}

// ---------------- SAGE layer: 128 nodes/CTA, 2 nodes/thread (R13 version) ----
#define SROW 68
template <int FOUT>
__global__ void klayer(const float* __restrict__ xin,
                       const float* __restrict__ Wl, const float* __restrict__ bl,
                       const float* __restrict__ Wr,
                       float* __restrict__ hout, int n_nodes) {
    extern __shared__ float dsm[];
    float* sX = dsm;
    float* sM = dsm + 128 * SROW;
    __shared__ float ssum[FOUT];
    __shared__ float sssq[FOUT];
    int tid = threadIdx.x;
    int nbase = blockIdx.x * 128;
    int r = tid >> 2;
    int q = tid & 3;
    if (tid < FOUT) { ssum[tid] = 0.f; sssq[tid] = 0.f; }

#pragma unroll
    for (int pp = 0; pp < 2; pp++) {
        int rr = r + pp * 64;
        int n = nbase + rr;
        bool ok = n < n_nodes;
        {
            const float4* xr = (const float4*)(xin + (size_t)(ok ? n : 0) * 64 + q * 16);
            float4 v0 = ok ? xr[0] : make_float4(0, 0, 0, 0);
            float4 v1 = ok ? xr[1] : make_float4(0, 0, 0, 0);
            float4 v2 = ok ? xr[2] : make_float4(0, 0, 0, 0);
            float4 v3 = ok ? xr[3] : make_float4(0, 0, 0, 0);
            *(float4*)&sX[rr * SROW + q * 16 + 0]  = v0;
            *(float4*)&sX[rr * SROW + q * 16 + 4]  = v1;
            *(float4*)&sX[rr * SROW + q * 16 + 8]  = v2;
            *(float4*)&sX[rr * SROW + q * 16 + 12] = v3;
        }
        {
            float a0[4] = {0, 0, 0, 0}, a1[4] = {0, 0, 0, 0};
            float a2[4] = {0, 0, 0, 0}, a3[4] = {0, 0, 0, 0};
            int beg = 0, end = 0;
            if (ok) { beg = g_off[n]; end = g_off[n + 1]; }
            int e = beg;
            for (; e + 2 <= end; e += 2) {
                const float4* p0 = (const float4*)(xin + (size_t)g_srcs[e] * 64 + q * 16);
                const float4* p1 = (const float4*)(xin + (size_t)g_srcs[e + 1] * 64 + q * 16);
                float4 u0 = p0[0], u1 = p0[1], u2 = p0[2], u3 = p0[3];
                float4 w0 = p1[0], w1 = p1[1], w2 = p1[2], w3 = p1[3];
                a0[0] += u0.x + w0.x; a0[1] += u0.y + w0.y; a0[2] += u0.z + w0.z; a0[3] += u0.w + w0.w;
                a1[0] += u1.x + w1.x; a1[1] += u1.y + w1.y; a1[2] += u1.z + w1.z; a1[3] += u1.w + w1.w;
                a2[0] += u2.x + w2.x; a2[1] += u2.y + w2.y; a2[2] += u2.z + w2.z; a2[3] += u2.w + w2.w;
                a3[0] += u3.x + w3.x; a3[1] += u3.y + w3.y; a3[2] += u3.z + w3.z; a3[3] += u3.w + w3.w;
            }
            if (e < end) {
                const float4* p0 = (const float4*)(xin + (size_t)g_srcs[e] * 64 + q * 16);
                float4 u0 = p0[0], u1 = p0[1], u2 = p0[2], u3 = p0[3];
                a0[0] += u0.x; a0[1] += u0.y; a0[2] += u0.z; a0[3] += u0.w;
                a1[0] += u1.x; a1[1] += u1.y; a1[2] += u1.z; a1[3] += u1.w;
                a2[0] += u2.x; a2[1] += u2.y; a2[2] += u2.z; a2[3] += u2.w;
                a3[0] += u3.x; a3[1] += u3.y; a3[2] += u3.z; a3[3] += u3.w;
            }
            float inv = 1.f / fmaxf((float)(end - beg), 1.f);
#pragma unroll
            for (int j = 0; j < 4; j++) {
                sM[rr * SROW + q * 16 + j]      = a0[j] * inv;
                sM[rr * SROW + q * 16 + 4 + j]  = a1[j] * inv;
                sM[rr * SROW + q * 16 + 8 + j]  = a2[j] * inv;
                sM[rr * SROW + q * 16 + 12 + j] = a3[j] * inv;
            }
        }
    }
    __syncthreads();

    const int CG = FOUT / 4;
    int c0 = q * CG;
    float acc0[CG], acc1[CG];
#pragma unroll
    for (int j = 0; j < CG; j++) { acc0[j] = bl[c0 + j]; acc1[j] = acc0[j]; }
#pragma unroll 4
    for (int k = 0; k < 64; k++) {
        float m0 = sM[r * SROW + k],        x0 = sX[r * SROW + k];
        float m1 = sM[(r + 64) * SROW + k], x1 = sX[(r + 64) * SROW + k];
        const float4* wl4 = (const float4*)(Wl + (size_t)k * FOUT + c0);
        const float4* wr4 = (const float4*)(Wr + (size_t)k * FOUT + c0);
#pragma unroll
        for (int jj = 0; jj < CG / 4; jj++) {
            float4 wl = wl4[jj], wr = wr4[jj];
            acc0[jj * 4 + 0] += m0 * wl.x + x0 * wr.x;
            acc0[jj * 4 + 1] += m0 * wl.y + x0 * wr.y;
            acc0[jj * 4 + 2] += m0 * wl.z + x0 * wr.z;
            acc0[jj * 4 + 3] += m0 * wl.w + x0 * wr.w;
            acc1[jj * 4 + 0] += m1 * wl.x + x1 * wr.x;
            acc1[jj * 4 + 1] += m1 * wl.y + x1 * wr.y;
            acc1[jj * 4 + 2] += m1 * wl.z + x1 * wr.z;
            acc1[jj * 4 + 3] += m1 * wl.w + x1 * wr.w;
        }
    }
    int n0 = nbase + r, n1 = nbase + r + 64;
    if (n0 < n_nodes) {
#pragma unroll
        for (int j = 0; j < CG; j++) {
            hout[(long long)n0 * FOUT + c0 + j] = acc0[j];
            atomicAdd(&ssum[c0 + j], acc0[j]);
            atomicAdd(&sssq[c0 + j], acc0[j] * acc0[j]);
        }
    }
    if (n1 < n_nodes) {
#pragma unroll
        for (int j = 0; j < CG; j++) {
            hout[(long long)n1 * FOUT + c0 + j] = acc1[j];
            atomicAdd(&ssum[c0 + j], acc1[j]);
            atomicAdd(&sssq[c0 + j], acc1[j] * acc1[j]);
        }
    }
    __syncthreads();
    if (tid < FOUT) {
        atomicAdd(&g_sum[tid], ssum[tid]);
        atomicAdd(&g_ssq[tid], sssq[tid]);
    }
}

// ---------------- BN finalize + apply (float4) ----------------
__global__ void kfinal(const float* __restrict__ g, const float* __restrict__ be,
                       int F, float invN) {
    int t = threadIdx.x;
    if (t >= F) return;
    float mu = g_sum[t] * invN;
    float var = fmaxf(g_ssq[t] * invN - mu * mu, 0.f);
    float sc = g[t] * rsqrtf(var + EPSBN);
    g_scale[t] = sc;
    g_shift[t] = be[t] - mu * sc;
}

__global__ void kbn(float* __restrict__ h, long long total4, int Fmask) {
    long long i = (long long)blockIdx.x * blockDim.x + threadIdx.x;
    if (i < total4) {
        long long i4 = i * 4;
        int c = (int)(i4 & Fmask);
        float4 v = *(float4*)&h[i4];
        float4 sc = *(float4*)&g_scale[c];
        float4 sh = *(float4*)&g_shift[c];
        v.x = fmaxf(v.x * sc.x + sh.x, 0.f);
        v.y = fmaxf(v.y * sc.y + sh.y, 0.f);
        v.z = fmaxf(v.z * sc.z + sh.z, 0.f);
        v.w = fmaxf(v.w * sc.w + sh.w, 0.f);
        *(float4*)&h[i4] = v;
    }
}

// ---------------- weight transposes (fp16) ----------------
__global__ void ktrans(const float* __restrict__ Wm2) {
    __shared__ float tile[32][33];
    int tx = threadIdx.x, ty = threadIdx.y;
    int bx = blockIdx.x, by = blockIdx.y;
#pragma unroll
    for (int i = 0; i < 4; i++)
        tile[ty + i * 8][tx] = Wm2[(by * 32 + ty + i * 8) * 1024 + bx * 32 + tx];
    __syncthreads();
#pragma unroll
    for (int i = 0; i < 4; i++)
        g_Wm2T[(size_t)(bx * 32 + ty + i * 8) * 1024 + by * 32 + tx] =
            __float2half_rn(tile[tx][ty + i * 8]);
}
__global__ void ktransW1(const float* __restrict__ Wm1) {
    int i = blockIdx.x * blockDim.x + threadIdx.x;
    if (i < 1024 * 32) {
        int n = i >> 5, k = i & 31;
        g_Wm1T[n * 32 + k] = __float2half_rn(Wm1[k * 1024 + n]);
    }
}

// ---------------- fused MLP: GEMM1 cached after nt=0, ldmatrix, 1-sync loop --
#define OFF_A    0                       // [128][36w] x2         36864
#define OFF_B20  36864                   // [256][36w] x2         73728
#define OFF_XH   110592                  // [128][20w]            10240
#define OFF_B10  120832                  // [64][20w] x2          10240
#define OFF_BM1  131072                  // 1024 f32               4096
#define OFF_W3H  135168                  // [16][132w] fp16x2      8448
#define OFF_BM2  143616                  // 256 f32                1024
#define MLP3_SMEM 144640

__global__ void __launch_bounds__(256, 1)
kmlp3(const float* __restrict__ xt2, const float* __restrict__ bm1,
      const float* __restrict__ bm2,
      const float* __restrict__ Wm3, const float* __restrict__ bm3,
      float* __restrict__ out_sm, float* __restrict__ out_lg, int n_nodes) {
    extern __shared__ __align__(16) char smem[];
    uint32_t sb = smem_u32(smem);
    float* sBm2 = (float*)(smem + OFF_BM2);
    float* sBm1 = (float*)(smem + OFF_BM1);
    uint32_t* sXw  = (uint32_t*)(smem + OFF_XH);
    uint32_t* sW3w = (uint32_t*)(smem + OFF_W3H);

    int t = threadIdx.x;
    int lane = t & 31;
    int wid = t >> 5;
    int wm = wid >> 2;
    int wn = wid & 3;
    int g = lane >> 2;
    int c4 = lane & 3;
    int base_m = blockIdx.x * 128;
    uint32_t* h1c = g_H1c + (size_t)blockIdx.x * 16 * 4096;

    uint32_t aBase = ((uint32_t)(wm * 64 + (lane & 7) + ((lane >> 3) & 1) * 8) * 36
                      + ((lane >> 4) & 1) * 4) * 4;
    uint32_t bBase = ((uint32_t)(wn * 64 + (lane & 7) + ((lane >> 4) & 1) * 8) * 36
                      + ((lane >> 3) & 1) * 4) * 4;

    // ---- stage X tile + bm1 ----
    for (int i = t; i < 128 * 16; i += 256) {
        int row = i >> 4, w = i & 15;
        int m = base_m + row;
        float f0 = 0.f, f1 = 0.f;
        if (m < n_nodes) {
            const float2 v = *(const float2*)(xt2 + (size_t)m * 32 + w * 2);
            f0 = v.x; f1 = v.y;
        }
        __half2 h = __floats2half2_rn(f0, f1);
        sXw[row * 20 + w] = *(uint32_t*)&h;
    }
    for (int i = t; i < 1024; i += 256) sBm1[i] = bm1[i];

    float L[4][2][4];
#pragma unroll
    for (int mf = 0; mf < 4; mf++)
#pragma unroll
        for (int h = 0; h < 2; h++)
#pragma unroll
            for (int e = 0; e < 4; e++) L[mf][h][e] = 0.f;

    for (int nt = 0; nt < 4; nt++) {
        if (t < 256) sBm2[t] = bm2[nt * 256 + t];
        for (int i = t; i < 2048; i += 256) {
            int o = i >> 7, kw = i & 127;
            int kg = nt * 256 + kw * 2;
            __half2 h = __floats2half2_rn(Wm3[(size_t)kg * 16 + o],
                                          Wm3[(size_t)(kg + 1) * 16 + o]);
            sW3w[o * 132 + kw] = *(uint32_t*)&h;
        }

        float acc[4][8][4];
#pragma unroll
        for (int mf = 0; mf < 4; mf++)
#pragma unroll
            for (int nf = 0; nf < 8; nf++)
#pragma unroll
                for (int e = 0; e < 4; e++) acc[mf][nf][e] = 0.f;

        if (nt == 0) {
            // ====== nt=0: compute GEMM1, cache H1 chunks ======
            {
                uint32_t b1off = sb + OFF_B10;
                if (t < 256) {
                    int row = t >> 2, c = t & 3;
                    cp16(b1off + row * 80 + c * 16, g_Wm1T + (size_t)row * 32 + c * 8);
                }
                cp_commit();
                uint32_t boff = sb + OFF_B20;
                for (int i = t; i < 2048; i += 256) {
                    int row = i >> 3, c = i & 7;
                    cp16(boff + row * 144 + c * 16,
                         g_Wm2T + (size_t)row * 1024 + c * 8);
                }
                uint32_t b1off1 = sb + OFF_B10 + 5120;
                if (t < 256) {
                    int row = t >> 2, c = t & 3;
                    cp16(b1off1 + row * 80 + c * 16,
                         g_Wm1T + (size_t)(64 + row) * 32 + c * 8);
                }
                cp_commit();
            }
            cp_wait0();
            __syncthreads();

            // GEMM1(0) -> sA[0] + g_H1c[0]
            {
                const uint32_t* B1 = (const uint32_t*)(smem + OFF_B10);
                uint32_t* sAw = (uint32_t*)(smem + OFF_A);
                float cc[8][4];
#pragma unroll
                for (int nf = 0; nf < 8; nf++)
#pragma unroll
                    for (int e = 0; e < 4; e++) cc[nf][e] = 0.f;
#pragma unroll
                for (int ks = 0; ks < 2; ks++) {
                    uint32_t a[4];
                    int r0 = wid * 16 + g;
                    a[0] = sXw[r0 * 20 + ks * 8 + c4];
                    a[1] = sXw[(r0 + 8) * 20 + ks * 8 + c4];
                    a[2] = sXw[r0 * 20 + ks * 8 + c4 + 4];
                    a[3] = sXw[(r0 + 8) * 20 + ks * 8 + c4 + 4];
#pragma unroll
                    for (int nf = 0; nf < 8; nf++) {
                        int nr = nf * 8 + g;
                        mma16(cc[nf], a, B1[nr * 20 + ks * 8 + c4], B1[nr * 20 + ks * 8 + c4 + 4]);
                    }
                }
                int r0 = wid * 16 + g;
#pragma unroll
                for (int nf = 0; nf < 8; nf++) {
                    int col = nf * 8 + c4 * 2;
                    float2 bv = *(const float2*)&sBm1[col];
                    __half2 p0 = __floats2half2_rn(fmaxf(cc[nf][0] + bv.x, 0.f),
                                                   fmaxf(cc[nf][1] + bv.y, 0.f));
                    __half2 p1 = __floats2half2_rn(fmaxf(cc[nf][2] + bv.x, 0.f),
                                                   fmaxf(cc[nf][3] + bv.y, 0.f));
                    sAw[r0 * 36 + nf * 4 + c4] = *(uint32_t*)&p0;
                    sAw[(r0 + 8) * 36 + nf * 4 + c4] = *(uint32_t*)&p1;
                    h1c[r0 * 32 + nf * 4 + c4] = *(uint32_t*)&p0;
                    h1c[(r0 + 8) * 32 + nf * 4 + c4] = *(uint32_t*)&p1;
                }
            }

            for (int kc = 0; kc < 16; kc++) {
                __syncthreads();
                if (kc < 15) {
                    uint32_t boff = sb + OFF_B20 + ((kc + 1) & 1) * 36864;
                    int kbase = (kc + 1) * 64;
                    for (int i = t; i < 2048; i += 256) {
                        int row = i >> 3, c = i & 7;
                        cp16(boff + row * 144 + c * 16,
                             g_Wm2T + (size_t)row * 1024 + kbase + c * 8);
                    }
                    if (kc + 2 <= 15) {
                        uint32_t b1off = sb + OFF_B10 + (kc & 1) * 5120;
                        if (t < 256) {
                            int row = t >> 2, c = t & 3;
                            cp16(b1off + row * 80 + c * 16,
                                 g_Wm1T + (size_t)((kc + 2) * 64 + row) * 32 + c * 8);
                        }
                    }
                    cp_commit();
                }
                // GEMM2(kc) via ldmatrix
                {
                    uint32_t Ab = sb + OFF_A + (kc & 1) * 18432u;
                    uint32_t Bb = sb + OFF_B20 + (kc & 1) * 36864u;
#pragma unroll
                    for (int ks = 0; ks < 4; ks++) {
                        uint32_t a[4][4];
#pragma unroll
                        for (int mf = 0; mf < 4; mf++)
                            ldsm4(a[mf], Ab + aBase + (mf * 576 + ks * 8) * 4);
#pragma unroll
                        for (int nfp = 0; nfp < 4; nfp++) {
                            uint32_t bf[4];
                            ldsm4(bf, Bb + bBase + (nfp * 576 + ks * 8) * 4);
#pragma unroll
                            for (int mf = 0; mf < 4; mf++) {
                                mma16(acc[mf][2 * nfp],     a[mf], bf[0], bf[1]);
                                mma16(acc[mf][2 * nfp + 1], a[mf], bf[2], bf[3]);
                            }
                        }
                    }
                }
                // GEMM1(kc+1)
                if (kc < 15) {
                    const uint32_t* B1 = (const uint32_t*)(smem + OFF_B10 + ((kc + 1) & 1) * 5120);
                    uint32_t* sAw = (uint32_t*)(smem + OFF_A + ((kc + 1) & 1) * 18432);
                    uint32_t* hc = h1c + (size_t)(kc + 1) * 4096;
                    float cc[8][4];
#pragma unroll
                    for (int nf = 0; nf < 8; nf++)
#pragma unroll
                        for (int e = 0; e < 4; e++) cc[nf][e] = 0.f;
#pragma unroll
                    for (int ks = 0; ks < 2; ks++) {
                        uint32_t a[4];
                        int r0 = wid * 16 + g;
                        a[0] = sXw[r0 * 20 + ks * 8 + c4];
                        a[1] = sXw[(r0 + 8) * 20 + ks * 8 + c4];
                        a[2] = sXw[r0 * 20 + ks * 8 + c4 + 4];
                        a[3] = sXw[(r0 + 8) * 20 + ks * 8 + c4 + 4];
#pragma unroll
                        for (int nf = 0; nf < 8; nf++) {
                            int nr = nf * 8 + g;
                            mma16(cc[nf], a, B1[nr * 20 + ks * 8 + c4], B1[nr * 20 + ks * 8 + c4 + 4]);
                        }
                    }
                    int r0 = wid * 16 + g;
#pragma unroll
                    for (int nf = 0; nf < 8; nf++) {
                        int col = (kc + 1) * 64 + nf * 8 + c4 * 2;
                        float2 bv = *(const float2*)&sBm1[col];
                        __half2 p0 = __floats2half2_rn(fmaxf(cc[nf][0] + bv.x, 0.f),
                                                       fmaxf(cc[nf][1] + bv.y, 0.f));
                        __half2 p1 = __floats2half2_rn(fmaxf(cc[nf][2] + bv.x, 0.f),
                                                       fmaxf(cc[nf][3] + bv.y, 0.f));
                        sAw[r0 * 36 + nf * 4 + c4] = *(uint32_t*)&p0;
                        sAw[(r0 + 8) * 36 + nf * 4 + c4] = *(uint32_t*)&p1;
                        hc[r0 * 32 + nf * 4 + c4] = *(uint32_t*)&p0;
                        hc[(r0 + 8) * 32 + nf * 4 + c4] = *(uint32_t*)&p1;
                    }
                }
                cp_wait0();
            }
        } else {
            // ====== nt>=1: cached H1, single-sync pipelined loop ======
            {
                uint32_t aoff = sb + OFF_A;
                const uint32_t* src = h1c;
                for (int i = t; i < 1024; i += 256) {
                    int row = i >> 3, c = i & 7;
                    cp16(aoff + row * 144 + c * 16, src + row * 32 + c * 4);
                }
                uint32_t boff = sb + OFF_B20;
                for (int i = t; i < 2048; i += 256) {
                    int row = i >> 3, c = i & 7;
                    cp16(boff + row * 144 + c * 16,
                         g_Wm2T + (size_t)(nt * 256 + row) * 1024 + c * 8);
                }
                cp_commit();
            }
            cp_wait0();
            for (int kc = 0; kc < 16; kc++) {
                __syncthreads();
                if (kc < 15) {
                    int k2 = kc + 1;
                    uint32_t aoff = sb + OFF_A + (k2 & 1) * 18432;
                    const uint32_t* src = h1c + (size_t)k2 * 4096;
                    for (int i = t; i < 1024; i += 256) {
                        int row = i >> 3, c = i & 7;
                        cp16(aoff + row * 144 + c * 16, src + row * 32 + c * 4);
                    }
                    uint32_t boff = sb + OFF_B20 + (k2 & 1) * 36864;
                    for (int i = t; i < 2048; i += 256) {
                        int row = i >> 3, c = i & 7;
                        cp16(boff + row * 144 + c * 16,
                             g_Wm2T + (size_t)(nt * 256 + row) * 1024 + k2 * 64 + c * 8);
                    }
                    cp_commit();
                }
                {
                    uint32_t Ab = sb + OFF_A + (kc & 1) * 18432u;
                    uint32_t Bb = sb + OFF_B20 + (kc & 1) * 36864u;
#pragma unroll
                    for (int ks = 0; ks < 4; ks++) {
                        uint32_t a[4][4];
#pragma unroll
                        for (int mf = 0; mf < 4; mf++)
                            ldsm4(a[mf], Ab + aBase + (mf * 576 + ks * 8) * 4);
#pragma unroll
                        for (int nfp = 0; nfp < 4; nfp++) {
                            uint32_t bf[4];
                            ldsm4(bf, Bb + bBase + (nfp * 576 + ks * 8) * 4);
#pragma unroll
                            for (int mf = 0; mf < 4; mf++) {
                                mma16(acc[mf][2 * nfp],     a[mf], bf[0], bf[1]);
                                mma16(acc[mf][2 * nfp + 1], a[mf], bf[2], bf[3]);
                            }
                        }
                    }
                }
                cp_wait0();
            }
        }

        // ---- GEMM3: logits += relu(acc + bm2) @ Wm3 ----
        {
            uint32_t b0f[4][2], b1f[4][2];
#pragma unroll
            for (int j = 0; j < 4; j++) {
                int kq = wn * 32 + 8 * j + c4;
#pragma unroll
                for (int h = 0; h < 2; h++) {
                    b0f[j][h] = sW3w[(h * 8 + g) * 132 + kq];
                    b1f[j][h] = sW3w[(h * 8 + g) * 132 + kq + 4];
                }
            }
#pragma unroll
            for (int j = 0; j < 4; j++) {
                int cA = wn * 64 + 16 * j + 2 * c4;
                float2 bva = *(const float2*)&sBm2[cA];
                float2 bvb = *(const float2*)&sBm2[cA + 8];
#pragma unroll
                for (int mf = 0; mf < 4; mf++) {
                    __half2 ha0 = __floats2half2_rn(fmaxf(acc[mf][2 * j][0] + bva.x, 0.f),
                                                    fmaxf(acc[mf][2 * j][1] + bva.y, 0.f));
                    __half2 ha1 = __floats2half2_rn(fmaxf(acc[mf][2 * j][2] + bva.x, 0.f),
                                                    fmaxf(acc[mf][2 * j][3] + bva.y, 0.f));
                    __half2 ha2 = __floats2half2_rn(fmaxf(acc[mf][2 * j + 1][0] + bvb.x, 0.f),
                                                    fmaxf(acc[mf][2 * j + 1][1] + bvb.y, 0.f));
                    __half2 ha3 = __floats2half2_rn(fmaxf(acc[mf][2 * j + 1][2] + bvb.x, 0.f),
                                                    fmaxf(acc[mf][2 * j + 1][3] + bvb.y, 0.f));
                    uint32_t a[4] = {*(uint32_t*)&ha0, *(uint32_t*)&ha1,
                                     *(uint32_t*)&ha2, *(uint32_t*)&ha3};
#pragma unroll
                    for (int h = 0; h < 2; h++)
                        mma16(L[mf][h], a, b0f[j][h], b1f[j][h]);
                }
            }
        }
        __syncthreads();
    }

    // ---- cross-warp logits reduce ----
    float* sLg = (float*)smem;
    for (int i = t; i < 2048; i += 256) sLg[i] = 0.f;
    __syncthreads();
#pragma unroll
    for (int mf = 0; mf < 4; mf++) {
        int R = wm * 64 + mf * 16 + g;
#pragma unroll
        for (int h = 0; h < 2; h++) {
            int col = h * 8 + 2 * c4;
            atomicAdd(&sLg[R * 16 + col],           L[mf][h][0]);
            atomicAdd(&sLg[R * 16 + col + 1],       L[mf][h][1]);
            atomicAdd(&sLg[(R + 8) * 16 + col],     L[mf][h][2]);
            atomicAdd(&sLg[(R + 8) * 16 + col + 1], L[mf][h][3]);
        }
    }
    __syncthreads();

    // ---- bias + softmax + store ----
    {
        int row = t >> 1, oh = t & 1;
        long long m = base_m + row;
        float lg8[8];
#pragma unroll
        for (int j = 0; j < 8; j++) lg8[j] = sLg[row * 16 + oh * 8 + j] + bm3[oh * 8 + j];
        float mx = lg8[0];
#pragma unroll
        for (int j = 1; j < 8; j++) mx = fmaxf(mx, lg8[j]);
        mx = fmaxf(mx, __shfl_xor_sync(0xffffffffu, mx, 1));
        float e[8];
        float s = 0.f;
#pragma unroll
        for (int j = 0; j < 8; j++) { e[j] = expf(lg8[j] - mx); s += e[j]; }
        s += __shfl_xor_sync(0xffffffffu, s, 1);
        float inv = 1.f / s;
        if (m < n_nodes) {
            float4* po = (float4*)&out_lg[m * 16 + oh * 8];
            float4* ps = (float4*)&out_sm[m * 16 + oh * 8];
            po[0] = make_float4(lg8[0], lg8[1], lg8[2], lg8[3]);
            po[1] = make_float4(lg8[4], lg8[5], lg8[6], lg8[7]);
            ps[0] = make_float4(e[0] * inv, e[1] * inv, e[2] * inv, e[3] * inv);
            ps[1] = make_float4(e[4] * inv, e[5] * inv, e[6] * inv, e[7] * inv);
        }
    }
}

// ---------------- launch ----------------
extern "C" void kernel_launch(void* const* d_in, const int* in_sizes, int n_in,
                              void* d_out, int out_size) {
    const float* x   = (const float*)d_in[0];
    const int*   ei  = (const int*)d_in[1];
    const float* W1l = (const float*)d_in[2];
    const float* b1l = (const float*)d_in[3];
    const float* W1r = (const float*)d_in[4];
    const float* g1  = (const float*)d_in[5];
    const float* be1 = (const float*)d_in[6];
    const float* W2l = (const float*)d_in[7];
    const float* b2l = (const float*)d_in[8];
    const float* W2r = (const float*)d_in[9];
    const float* g2  = (const float*)d_in[10];
    const float* be2 = (const float*)d_in[11];
    const float* Wm1 = (const float*)d_in[12];
    const float* bm1 = (const float*)d_in[13];
    const float* Wm2 = (const float*)d_in[14];
    const float* bm2 = (const float*)d_in[15];
    const float* Wm3 = (const float*)d_in[16];
    const float* bm3 = (const float*)d_in[17];

    const int n = in_sizes[0] / FIN;             // 100000
    const int E = in_sizes[1] / 2;               // 1600000

    float* out = (float*)d_out;
    float* out_sm = out;
    float* out_lg = out + (long long)n * 16;
    float* xt1    = out + (long long)n * 32;
    float* xt2    = out + (long long)n * 96;

    const float invN = 1.f / (float)n;
    const int layer_grid = (n + 127) / 128;
    const int LAY_SMEM = 2 * 128 * SROW * 4;     // 69632

    cudaFuncSetAttribute(kmlp3, cudaFuncAttributeMaxDynamicSharedMemorySize, MLP3_SMEM);
    cudaFuncSetAttribute(klayer<64>, cudaFuncAttributeMaxDynamicSharedMemorySize, LAY_SMEM);
    cudaFuncSetAttribute(klayer<32>, cudaFuncAttributeMaxDynamicSharedMemorySize, LAY_SMEM);

    // ----- CSR build -----
    k0_zero<<<512, 256>>>();
    khist<<<1024, 256>>>(ei, E);
    kscan<<<1, 1024>>>(E);
    kfill<<<1024, 256>>>(ei, E);

    // ----- layer 1 -----
    kzstats<<<1, 64>>>();
    klayer<64><<<layer_grid, 256, LAY_SMEM>>>(x, W1l, b1l, W1r, xt1, n);
    kfinal<<<1, 64>>>(g1, be1, 64, invN);
    kbn<<<(int)(((long long)n * 16 + 255) / 256), 256>>>(xt1, (long long)n * 16, 63);

    // ----- layer 2 -----
    kzstats<<<1, 64>>>();
    klayer<32><<<layer_grid, 256, LAY_SMEM>>>(xt1, W2l, b2l, W2r, xt2, n);
    kfinal<<<1, 32>>>(g2, be2, 32, invN);
    kbn<<<(int)(((long long)n * 8 + 255) / 256), 256>>>(xt2, (long long)n * 8, 31);

    // ----- fused MLP -----
    dim3 tb(32, 8);
    dim3 tg(32, 32);
    ktrans<<<tg, tb>>>(Wm2);
    ktransW1<<<128, 256>>>(Wm1);
    kmlp3<<<NPAD / 128, 256, MLP3_SMEM>>>(xt2, bm1, bm2, Wm3, bm3, out_sm, out_lg, n);
}